// round 7
// baseline (speedup 1.0000x reference)
#include <cuda_runtime.h>

// FWHT over last axis, DIM=4096 = 16*16*16, fp32, scale 1/64.
// H_4096 = H_16 (x) H_16 (x) H_16 : three in-register H16 passes over the
// three base-16 digits (n2,n1,n0) of the index, with two shared-memory
// transposes in between. One CTA (256 threads) per row; each thread owns
// 16 floats in registers.
//
// Shared layout: phys(n2,n1,n0) = 272*n2 + 16*n1 + ((n0+n1)&15)
//   - +16 pad per 256-word block makes the n2 stride ≡ 16 (mod 32)
//   - the (n0+n1)&15 rotation de-conflicts the phase-A vectored-ish writes
// All four smem access phases are 32-distinct-bank per warp instruction
// (verified by hand: parity class 16*((n2+n1)&1) or 16*((n2+k)&1) splits the
// warp halves onto disjoint bank halves, rotation makes offsets distinct).

#define FWHT_DIM 4096

__device__ __forceinline__ void h16(float (&v)[16]) {
#pragma unroll
    for (int h = 1; h < 16; h <<= 1) {
#pragma unroll
        for (int i = 0; i < 16; i++) {
            if (!(i & h)) {
                float a = v[i];
                float b = v[i + h];
                v[i]     = a + b;
                v[i + h] = a - b;
            }
        }
    }
}

__global__ __launch_bounds__(256)
void fwht4096_kernel(const float* __restrict__ x, float* __restrict__ y) {
    __shared__ float s[16 * 272];   // 17408 B

    const int t = threadIdx.x;                    // 0..255
    const size_t row = (size_t)blockIdx.x * FWHT_DIM;
    const float* __restrict__ xr = x + row;
    float* __restrict__ yr = y + row;

    float v[16];

    // ---- Phase 0: load 16 contiguous floats (digit n0 varies), 4x LDG.128 ----
    {
        const float4* p = reinterpret_cast<const float4*>(xr + t * 16);
#pragma unroll
        for (int j = 0; j < 4; j++) {
            float4 f = __ldcs(p + j);
            v[4 * j + 0] = f.x;
            v[4 * j + 1] = f.y;
            v[4 * j + 2] = f.z;
            v[4 * j + 3] = f.w;
        }
    }

    // H16 over n0 (strides 1,2,4,8)
    h16(v);

    // ---- Phase A: scatter to shared. Thread owns (n2 = t>>4, n1 = t&15),
    //      v[j] is logical n0 = j. Rotated offset keeps banks conflict-free
    //      and v-index compile-time constant. ----
    {
        const int n2 = t >> 4;
        const int n1 = t & 15;
        const int base = n2 * 272 + n1 * 16;
#pragma unroll
        for (int j = 0; j < 16; j++)
            s[base + ((j + n1) & 15)] = v[j];
    }
    __syncthreads();

    // ---- Phase B: thread owns (n2 = t>>4, n0 = t&15), loop gathers n1 = k ----
    {
        const int n2 = t >> 4;
        const int n0 = t & 15;
        const int base = n2 * 272;
#pragma unroll
        for (int k = 0; k < 16; k++)
            v[k] = s[base + 16 * k + ((n0 + k) & 15)];

        h16(v);   // H16 over n1 (strides 16..128)

#pragma unroll
        for (int k = 0; k < 16; k++)
            s[base + 16 * k + ((n0 + k) & 15)] = v[k];
    }
    __syncthreads();

    // ---- Phase C: thread owns (n1 = t>>4, n0 = t&15), loop gathers n2 = k ----
    {
        const int n1 = t >> 4;
        const int n0 = t & 15;
        const int off = 16 * n1 + ((n0 + n1) & 15);
#pragma unroll
        for (int k = 0; k < 16; k++)
            v[k] = s[272 * k + off];

        h16(v);   // H16 over n2 (strides 256..2048)

        // Scale and store: logical index = 256*k + 16*n1 + n0.
        // Per warp STG.32 instruction: 32 consecutive words -> one 128B line.
        const float sc = 0.015625f;   // 1/64 = 1/sqrt(4096)
        const int obase = 16 * n1 + n0;
#pragma unroll
        for (int k = 0; k < 16; k++)
            __stcs(yr + 256 * k + obase, v[k] * sc);
    }
}

extern "C" void kernel_launch(void* const* d_in, const int* in_sizes, int n_in,
                              void* d_out, int out_size) {
    (void)n_in;
    const float* x = (const float*)d_in[0];
    float* y = (float*)d_out;
    const int rows = in_sizes[0] / FWHT_DIM;   // 16384 for [8,2048,4096]
    (void)out_size;
    fwht4096_kernel<<<rows, 256>>>(x, y);
}